// round 8
// baseline (speedup 1.0000x reference)
#include <cuda_runtime.h>
#include <cstdint>
#include <math.h>

#define N_EL 4096
#define N_NB 32
#define F_IN 5
#define EDGE_FEAT 32
#define FEAT 256
#define CUTOFF_F 3.0f
#define TILE_BYTES (N_NB * FEAT * 4)   // 32 KB per (role, n)

// Fused kernel: grid (N_EL, 2). blockIdx.y==0 -> Gamma, ==1 -> edge_features.
// Compute into smem tile, then one TMA bulk store (32 KB contiguous) to gmem.
__global__ __launch_bounds__(256)
void fused_kernel(
    const float* __restrict__ r,        // [N,3]
    const float* __restrict__ r_nb,     // [N,K,3]
    const float* __restrict__ fkern,    // [N,5,32]
    const float* __restrict__ fbias,    // [N,32]
    const float* __restrict__ Wg,       // [32,256]
    const float* __restrict__ ekern,    // [N,5,256]
    const float* __restrict__ ebias,    // [N,256]
    const int*   __restrict__ s,        // [N]
    const int*   __restrict__ s_nb,     // [N,K]
    float*       __restrict__ out)      // [2, N, K, 256]
{
    const int n    = blockIdx.x;
    const int role = blockIdx.y;        // block-uniform
    const int tid  = threadIdx.x;

    __shared__ __align__(16)  float sh_feats[N_NB][8];        // premult feats + bias-scale
    __shared__ __align__(16)  float sh_fk[F_IN][EDGE_FEAT];   // 5x32  (role 0)
    __shared__ __align__(16)  float sh_fb[EDGE_FEAT];         // 32    (role 0)
    __shared__ __align__(16)  float sh_fkW[6][FEAT];          // rows 0-4 Fk@W, row 5 fb@W
    __shared__ __align__(128) float sh_out[N_NB][FEAT];       // 32 KB output tile

    // ---- feats + envelope (threads 0..31) ----
    if (tid < N_NB) {
        const int k = tid;
        float rx = r[n * 3 + 0], ry = r[n * 3 + 1], rz = r[n * 3 + 2];
        const float* rn = &r_nb[((size_t)n * N_NB + k) * 3];
        float dx = rn[0] - rx, dy = rn[1] - ry, dz = rn[2] - rz;
        float dist = sqrtf(dx * dx + dy * dy + dz * dz);
        float env = 0.0f;
        if (dist < CUTOFF_F) {
            float x = dist * (1.0f / CUTOFF_F);
            if (x > 1.0f) x = 1.0f;
            env = 0.5f * (cospif(x) + 1.0f);
        }
        float same = (s[n] == s_nb[(size_t)n * N_NB + k]) ? 1.0f : 0.0f;
        // role 0: premultiply env into feats, bias-scale = env
        // role 1: raw feats, bias-scale = 1
        float m  = (role == 0) ? env : 1.0f;
        float4* fp = (float4*)&sh_feats[k][0];
        fp[0] = make_float4(dx * m, dy * m, dz * m, dist * m);
        fp[1] = make_float4(same * m, m, 0.0f, 0.0f);
    }

    // ---- role 0: stage per-n filter params (threads 64..255) ----
    if (role == 0 && tid >= 64) {
        const int i = tid - 64;                    // 0..191
        if (i < F_IN * EDGE_FEAT) {
            sh_fk[i / EDGE_FEAT][i % EDGE_FEAT] = fkern[(size_t)n * F_IN * EDGE_FEAT + i];
        } else {
            sh_fb[i - F_IN * EDGE_FEAT] = fbias[(size_t)n * EDGE_FEAT + (i - F_IN * EDGE_FEAT)];
        }
    }
    __syncthreads();

    const int dg = tid & 63;      // 0..63 varies within warp -> conflict-free STS
    const int kq = tid >> 6;      // 0..3  uniform within warp -> broadcast feat loads
    const int d0 = dg * 4;

    float4 c0, c1, c2, c3, c4, cb;

    if (role == 0) {
        // ---- FkW = Fk @ Wg, fbW = fb @ Wg; one d column per thread ----
        const int d = tid;
        float a0 = 0.f, a1 = 0.f, a2 = 0.f, a3 = 0.f, a4 = 0.f, ab = 0.f;
#pragma unroll
        for (int e4 = 0; e4 < EDGE_FEAT; e4 += 4) {
            float4 vb = *(const float4*)&sh_fb[e4];
            float4 v0 = *(const float4*)&sh_fk[0][e4];
            float4 v1 = *(const float4*)&sh_fk[1][e4];
            float4 v2 = *(const float4*)&sh_fk[2][e4];
            float4 v3 = *(const float4*)&sh_fk[3][e4];
            float4 v4 = *(const float4*)&sh_fk[4][e4];
            float w0 = Wg[(e4 + 0) * FEAT + d];
            float w1 = Wg[(e4 + 1) * FEAT + d];
            float w2 = Wg[(e4 + 2) * FEAT + d];
            float w3 = Wg[(e4 + 3) * FEAT + d];
            ab += vb.x * w0 + vb.y * w1 + vb.z * w2 + vb.w * w3;
            a0 += v0.x * w0 + v0.y * w1 + v0.z * w2 + v0.w * w3;
            a1 += v1.x * w0 + v1.y * w1 + v1.z * w2 + v1.w * w3;
            a2 += v2.x * w0 + v2.y * w1 + v2.z * w2 + v2.w * w3;
            a3 += v3.x * w0 + v3.y * w1 + v3.z * w2 + v3.w * w3;
            a4 += v4.x * w0 + v4.y * w1 + v4.z * w2 + v4.w * w3;
        }
        sh_fkW[0][d] = a0; sh_fkW[1][d] = a1; sh_fkW[2][d] = a2;
        sh_fkW[3][d] = a3; sh_fkW[4][d] = a4; sh_fkW[5][d] = ab;
        __syncthreads();

        c0 = *(const float4*)&sh_fkW[0][d0];
        c1 = *(const float4*)&sh_fkW[1][d0];
        c2 = *(const float4*)&sh_fkW[2][d0];
        c3 = *(const float4*)&sh_fkW[3][d0];
        c4 = *(const float4*)&sh_fkW[4][d0];
        cb = *(const float4*)&sh_fkW[5][d0];
    } else {
        const float* base = &ekern[(size_t)n * F_IN * FEAT + d0];
        c0 = *(const float4*)&base[0 * FEAT];
        c1 = *(const float4*)&base[1 * FEAT];
        c2 = *(const float4*)&base[2 * FEAT];
        c3 = *(const float4*)&base[3 * FEAT];
        c4 = *(const float4*)&base[4 * FEAT];
        cb = *(const float4*)&ebias[(size_t)n * FEAT + d0];
    }

    // ---- branch-free main loop: 8 k's per thread, STS.128 into tile ----
#pragma unroll
    for (int kk = 0; kk < 8; kk++) {
        const int k = kq * 8 + kk;
        float4 fa = *(const float4*)&sh_feats[k][0];   // f0..f3 (broadcast LDS)
        float4 fe = *(const float4*)&sh_feats[k][4];   // f4, bs

        const float f0 = fa.x, f1 = fa.y, f2 = fa.z, f3 = fa.w;
        const float f4 = fe.x, bs = fe.y;

        float4 o;
        o.x = bs * cb.x + f0 * c0.x + f1 * c1.x + f2 * c2.x + f3 * c3.x + f4 * c4.x;
        o.y = bs * cb.y + f0 * c0.y + f1 * c1.y + f2 * c2.y + f3 * c3.y + f4 * c4.y;
        o.z = bs * cb.z + f0 * c0.z + f1 * c1.z + f2 * c2.z + f3 * c3.z + f4 * c4.z;
        o.w = bs * cb.w + f0 * c0.w + f1 * c1.w + f2 * c2.w + f3 * c3.w + f4 * c4.w;

        *(float4*)&sh_out[k][d0] = o;
    }
    __syncthreads();

    // ---- one TMA bulk store: smem tile (32 KB contiguous) -> gmem ----
    if (tid == 0) {
        const size_t EOFF = (size_t)N_EL * N_NB * FEAT;
        float* gdst = &out[(size_t)role * EOFF + (size_t)n * N_NB * FEAT];
        unsigned int saddr;
        asm("{ .reg .u64 t; cvta.to.shared.u64 t, %1; cvt.u32.u64 %0, t; }"
            : "=r"(saddr) : "l"(&sh_out[0][0]));
        asm volatile("fence.proxy.async.shared::cta;" ::: "memory");
        asm volatile(
            "cp.async.bulk.global.shared::cta.bulk_group [%0], [%1], %2;"
            :: "l"(gdst), "r"(saddr), "r"((unsigned int)TILE_BYTES) : "memory");
        asm volatile("cp.async.bulk.commit_group;" ::: "memory");
        asm volatile("cp.async.bulk.wait_group.read 0;" ::: "memory");
    }
}

extern "C" void kernel_launch(void* const* d_in, const int* in_sizes, int n_in,
                              void* d_out, int out_size) {
    const float* r     = (const float*)d_in[0];
    const float* r_nb  = (const float*)d_in[1];
    const float* fkern = (const float*)d_in[2];
    const float* fbias = (const float*)d_in[3];
    const float* Wg    = (const float*)d_in[4];
    const float* ekern = (const float*)d_in[5];
    const float* ebias = (const float*)d_in[6];
    const int*   s     = (const int*)d_in[7];
    const int*   s_nb  = (const int*)d_in[8];
    float* out = (float*)d_out;

    dim3 grid(N_EL, 2);
    fused_kernel<<<grid, 256>>>(r, r_nb, fkern, fbias, Wg, ekern, ebias, s, s_nb, out);
}

// round 9
// speedup vs baseline: 1.2499x; 1.2499x over previous
#include <cuda_runtime.h>
#include <cstdint>
#include <math.h>

#define N_EL 4096
#define N_NB 32
#define F_IN 5
#define EDGE_FEAT 32
#define FEAT 256
#define CUTOFF_F 3.0f

// packed f32x2 helpers (sm_100+): one instr = two independent fp32 ops
#define PACK2(dst, a, b) \
    asm("mov.b64 %0, {%1,%2};" : "=l"(dst) : "f"(a), "f"(b))
#define FMA2(d, a, b, c) \
    asm("fma.rn.f32x2 %0, %1, %2, %3;" : "=l"(d) : "l"(a), "l"(b), "l"(c))
#define MUL2(d, a, b) \
    asm("mul.rn.f32x2 %0, %1, %2;" : "=l"(d) : "l"(a), "l"(b))

typedef unsigned long long u64;

// Fused kernel: grid (N_EL, 2). blockIdx.y==0 -> Gamma, ==1 -> edge_features.
__global__ __launch_bounds__(256)
void fused_kernel(
    const float* __restrict__ r,        // [N,3]
    const float* __restrict__ r_nb,     // [N,K,3]
    const float* __restrict__ fkern,    // [N,5,32]
    const float* __restrict__ fbias,    // [N,32]
    const float* __restrict__ Wg,       // [32,256]
    const float* __restrict__ ekern,    // [N,5,256]
    const float* __restrict__ ebias,    // [N,256]
    const int*   __restrict__ s,        // [N]
    const int*   __restrict__ s_nb,     // [N,K]
    float*       __restrict__ out)      // [2, N, K, 256]
{
    const int n    = blockIdx.x;
    const int role = blockIdx.y;        // block-uniform
    const int tid  = threadIdx.x;

    // feats duplicated into (f,f) pairs: [f0f0 f1f1 f2f2 f3f3 f4f4 bsbs]
    __shared__ __align__(16) float sh_feats[N_NB][12];
    __shared__ __align__(16) float sh_fk[F_IN][EDGE_FEAT];   // 5x32  (role 0)
    __shared__ __align__(16) float sh_fb[EDGE_FEAT];         // 32    (role 0)
    __shared__ __align__(16) float sh_fkW[6][FEAT];          // rows 0-4 Fk@W, row 5 fb@W

    // ---- feats + envelope (threads 0..31) ----
    if (tid < N_NB) {
        const int k = tid;
        float rx = r[n * 3 + 0], ry = r[n * 3 + 1], rz = r[n * 3 + 2];
        const float* rn = &r_nb[((size_t)n * N_NB + k) * 3];
        float dx = rn[0] - rx, dy = rn[1] - ry, dz = rn[2] - rz;
        float dist = sqrtf(dx * dx + dy * dy + dz * dz);
        float env = 0.0f;
        if (dist < CUTOFF_F) {
            float x = dist * (1.0f / CUTOFF_F);
            if (x > 1.0f) x = 1.0f;
            env = 0.5f * (cospif(x) + 1.0f);
        }
        float same = (s[n] == s_nb[(size_t)n * N_NB + k]) ? 1.0f : 0.0f;
        // role 0: premultiply env into feats, bias-scale = env; role 1: raw, bs = 1
        float m = (role == 0) ? env : 1.0f;
        float f0 = dx * m, f1 = dy * m, f2 = dz * m, f3 = dist * m, f4 = same * m;
        float4* fp = (float4*)&sh_feats[k][0];
        fp[0] = make_float4(f0, f0, f1, f1);
        fp[1] = make_float4(f2, f2, f3, f3);
        fp[2] = make_float4(f4, f4, m, m);
    }

    // ---- role 0: stage per-n filter params (threads 64..255) ----
    if (role == 0 && tid >= 64) {
        const int i = tid - 64;                    // 0..191
        if (i < F_IN * EDGE_FEAT) {
            sh_fk[i / EDGE_FEAT][i % EDGE_FEAT] = fkern[(size_t)n * F_IN * EDGE_FEAT + i];
        } else {
            sh_fb[i - F_IN * EDGE_FEAT] = fbias[(size_t)n * EDGE_FEAT + (i - F_IN * EDGE_FEAT)];
        }
    }
    __syncthreads();

    const int dg = tid & 63;      // 0..63 varies within warp -> coalesced stores
    const int kq = tid >> 6;      // 0..3  uniform within warp -> broadcast feat loads
    const int d0 = dg * 4;

    float4 c0, c1, c2, c3, c4, cb;

    if (role == 0) {
        // ---- FkW = Fk @ Wg, fbW = fb @ Wg; one d column per thread ----
        const int d = tid;
        float a0 = 0.f, a1 = 0.f, a2 = 0.f, a3 = 0.f, a4 = 0.f, ab = 0.f;
#pragma unroll
        for (int e4 = 0; e4 < EDGE_FEAT; e4 += 4) {
            float4 vb = *(const float4*)&sh_fb[e4];
            float4 v0 = *(const float4*)&sh_fk[0][e4];
            float4 v1 = *(const float4*)&sh_fk[1][e4];
            float4 v2 = *(const float4*)&sh_fk[2][e4];
            float4 v3 = *(const float4*)&sh_fk[3][e4];
            float4 v4 = *(const float4*)&sh_fk[4][e4];
            float w0 = Wg[(e4 + 0) * FEAT + d];
            float w1 = Wg[(e4 + 1) * FEAT + d];
            float w2 = Wg[(e4 + 2) * FEAT + d];
            float w3 = Wg[(e4 + 3) * FEAT + d];
            ab += vb.x * w0 + vb.y * w1 + vb.z * w2 + vb.w * w3;
            a0 += v0.x * w0 + v0.y * w1 + v0.z * w2 + v0.w * w3;
            a1 += v1.x * w0 + v1.y * w1 + v1.z * w2 + v1.w * w3;
            a2 += v2.x * w0 + v2.y * w1 + v2.z * w2 + v2.w * w3;
            a3 += v3.x * w0 + v3.y * w1 + v3.z * w2 + v3.w * w3;
            a4 += v4.x * w0 + v4.y * w1 + v4.z * w2 + v4.w * w3;
        }
        sh_fkW[0][d] = a0; sh_fkW[1][d] = a1; sh_fkW[2][d] = a2;
        sh_fkW[3][d] = a3; sh_fkW[4][d] = a4; sh_fkW[5][d] = ab;
        __syncthreads();

        c0 = *(const float4*)&sh_fkW[0][d0];
        c1 = *(const float4*)&sh_fkW[1][d0];
        c2 = *(const float4*)&sh_fkW[2][d0];
        c3 = *(const float4*)&sh_fkW[3][d0];
        c4 = *(const float4*)&sh_fkW[4][d0];
        cb = *(const float4*)&sh_fkW[5][d0];
    } else {
        const float* base = &ekern[(size_t)n * F_IN * FEAT + d0];
        c0 = *(const float4*)&base[0 * FEAT];
        c1 = *(const float4*)&base[1 * FEAT];
        c2 = *(const float4*)&base[2 * FEAT];
        c3 = *(const float4*)&base[3 * FEAT];
        c4 = *(const float4*)&base[4 * FEAT];
        cb = *(const float4*)&ebias[(size_t)n * FEAT + d0];
    }

    // ---- pack coefficient pairs once (loop-invariant) ----
    u64 c0xy, c0zw, c1xy, c1zw, c2xy, c2zw, c3xy, c3zw, c4xy, c4zw, cbxy, cbzw;
    PACK2(c0xy, c0.x, c0.y); PACK2(c0zw, c0.z, c0.w);
    PACK2(c1xy, c1.x, c1.y); PACK2(c1zw, c1.z, c1.w);
    PACK2(c2xy, c2.x, c2.y); PACK2(c2zw, c2.z, c2.w);
    PACK2(c3xy, c3.x, c3.y); PACK2(c3zw, c3.z, c3.w);
    PACK2(c4xy, c4.x, c4.y); PACK2(c4zw, c4.z, c4.w);
    PACK2(cbxy, cb.x, cb.y); PACK2(cbzw, cb.z, cb.w);

    // ---- branch-free main loop: 8 k's per thread, f32x2 math, v2.b64 stores ----
    const size_t EOFF  = (size_t)N_EL * N_NB * FEAT;
    float* obase = &out[(size_t)role * EOFF + (size_t)n * N_NB * FEAT
                        + (size_t)kq * 8 * FEAT + d0];

#pragma unroll
    for (int kk = 0; kk < 8; kk++) {
        const int k = kq * 8 + kk;
        const u64* fpk = (const u64*)&sh_feats[k][0];
        ulonglong2 p01 = *(const ulonglong2*)(fpk + 0);   // f0f0, f1f1
        ulonglong2 p23 = *(const ulonglong2*)(fpk + 2);   // f2f2, f3f3
        ulonglong2 p45 = *(const ulonglong2*)(fpk + 4);   // f4f4, bsbs

        u64 oxy, ozw;
        MUL2(oxy, p45.y, cbxy);
        MUL2(ozw, p45.y, cbzw);
        FMA2(oxy, p01.x, c0xy, oxy);  FMA2(ozw, p01.x, c0zw, ozw);
        FMA2(oxy, p01.y, c1xy, oxy);  FMA2(ozw, p01.y, c1zw, ozw);
        FMA2(oxy, p23.x, c2xy, oxy);  FMA2(ozw, p23.x, c2zw, ozw);
        FMA2(oxy, p23.y, c3xy, oxy);  FMA2(ozw, p23.y, c3zw, ozw);
        FMA2(oxy, p45.x, c4xy, oxy);  FMA2(ozw, p45.x, c4zw, ozw);

        asm volatile("st.global.cs.v2.b64 [%0], {%1, %2};"
                     :: "l"(obase + kk * FEAT), "l"(oxy), "l"(ozw) : "memory");
    }
}

extern "C" void kernel_launch(void* const* d_in, const int* in_sizes, int n_in,
                              void* d_out, int out_size) {
    const float* r     = (const float*)d_in[0];
    const float* r_nb  = (const float*)d_in[1];
    const float* fkern = (const float*)d_in[2];
    const float* fbias = (const float*)d_in[3];
    const float* Wg    = (const float*)d_in[4];
    const float* ekern = (const float*)d_in[5];
    const float* ebias = (const float*)d_in[6];
    const int*   s     = (const int*)d_in[7];
    const int*   s_nb  = (const int*)d_in[8];
    float* out = (float*)d_out;

    dim3 grid(N_EL, 2);
    fused_kernel<<<grid, 256>>>(r, r_nb, fkern, fbias, Wg, ekern, ebias, s, s_nb, out);
}